// round 7
// baseline (speedup 1.0000x reference)
#include <cuda_runtime.h>

#define H      256
#define OUTN   200
#define DIN    20
#define TSTEPS 150
#define BETA   0.9f
#define THR    1.0f

// Transposed weights scratch: Wt[i*H + j] = W[j][i]; Wout padded to 256 cols.
// Region order gives every layer a valid overrun pad for distance-3 (12-row)
// prefetch; the 4096-float tail pad covers WOt's lookahead.
#define OFF_W1 0
#define OFF_W2 5120
#define OFF_W3 (5120 + 65536)
#define OFF_W4 (5120 + 2*65536)
#define OFF_WO (5120 + 3*65536)
#define WT_TOTAL (5120 + 4*65536)
__device__ float g_Wt[WT_TOTAL + 4096];

typedef unsigned long long u64;

__device__ __forceinline__ u64 ffma2(u64 a, u64 b, u64 c) {
    u64 d;
    asm("fma.rn.f32x2 %0, %1, %2, %3;" : "=l"(d) : "l"(a), "l"(b), "l"(c));
    return d;
}
__device__ __forceinline__ u64 pack2(float w) {
    u64 d;
    asm("mov.b64 %0, {%1, %1};" : "=l"(d) : "f"(w));
    return d;
}
__device__ __forceinline__ void unpack2(u64 a, float& x, float& y) {
    asm("mov.b64 {%0, %1}, %2;" : "=f"(x), "=f"(y) : "l"(a));
}

// GEMM slice: thread computes 2 output neurons (j0, j0+128) over K inputs for
// PT packed row-pairs. JT=2 gives 2x SMEM-operand reuse; rolling weight
// registers give distance-3-group (12-row) LDG prefetch (~336cyc cover vs
// 262cyc L2-far) at 2 warps/SMSP.
// Accumulation order per (p,j) is ascending-i — bit-identical to prior rounds.
template<int K, int PT>
__device__ __forceinline__ void gemm2(const float* __restrict__ Wt,
                                      const float2* __restrict__ sb,
                                      int j0, u64* __restrict__ acc) {
#pragma unroll
    for (int q = 0; q < 2*PT; q++) acc[q] = 0ull;
    const float* __restrict__ Wa = Wt + j0;
    const float* __restrict__ Wb = Wt + j0 + 128;

    float a0[4], a1[4], a2[4], b0[4], b1[4], b2[4];
#pragma unroll
    for (int q = 0; q < 4; q++) {
        a0[q] = Wa[q*H];        b0[q] = Wb[q*H];
        a1[q] = Wa[(4+q)*H];    b1[q] = Wb[(4+q)*H];
        a2[q] = Wa[(8+q)*H];    b2[q] = Wb[(8+q)*H];
    }
#pragma unroll 2
    for (int i = 0; i < K; i += 4) {
        float fa[4], fb[4];
#pragma unroll
        for (int q = 0; q < 4; q++) {        // prefetch group i+12 (overruns -> pad)
            fa[q] = Wa[(i+12+q)*H];
            fb[q] = Wb[(i+12+q)*H];
        }
        u64 A0 = pack2(a0[0]), A1 = pack2(a0[1]), A2 = pack2(a0[2]), A3 = pack2(a0[3]);
        u64 B0 = pack2(b0[0]), B1 = pack2(b0[1]), B2 = pack2(b0[2]), B3 = pack2(b0[3]);
#pragma unroll
        for (int p = 0; p < PT; p++) {
            const ulonglong2* s = reinterpret_cast<const ulonglong2*>(sb + p*H + i);
            ulonglong2 ab = s[0];   // pairs (i),(i+1) — already f32x2-packed
            ulonglong2 cd = s[1];   // pairs (i+2),(i+3)
            acc[p]    = ffma2(A0, ab.x, acc[p]);
            acc[p]    = ffma2(A1, ab.y, acc[p]);
            acc[p]    = ffma2(A2, cd.x, acc[p]);
            acc[p]    = ffma2(A3, cd.y, acc[p]);
            acc[PT+p] = ffma2(B0, ab.x, acc[PT+p]);
            acc[PT+p] = ffma2(B1, ab.y, acc[PT+p]);
            acc[PT+p] = ffma2(B2, cd.x, acc[PT+p]);
            acc[PT+p] = ffma2(B3, cd.y, acc[PT+p]);
        }
#pragma unroll
        for (int q = 0; q < 4; q++) {
            a0[q] = a1[q]; b0[q] = b1[q];
            a1[q] = a2[q]; b1[q] = b2[q];
            a2[q] = fa[q]; b2[q] = fb[q];
        }
    }
}

// Leaky update (reset from PREVIOUS membrane, subtract) + spike write, 2 j's.
template<int PT>
__device__ __forceinline__ void leaky2(const u64* __restrict__ acc, float c0, float c1,
                                       float* __restrict__ m, float2* __restrict__ dst,
                                       int j0) {
#pragma unroll
    for (int js = 0; js < 2; js++) {
        float bs = js ? c1 : c0;
        int j = j0 + js*128;
#pragma unroll
        for (int p = 0; p < PT; p++) {
            float i0, i1; unpack2(acc[js*PT + p], i0, i1);
            int mi = (js*PT + p)*2;
            float a = m[mi], b = m[mi+1];
            float ra = (a > THR) ? THR : 0.f;
            float rb = (b > THR) ? THR : 0.f;
            a = BETA*a + (i0 + bs) - ra;
            b = BETA*b + (i1 + bs) - rb;
            m[mi] = a; m[mi+1] = b;
            dst[p*H + j] = make_float2(a > THR ? 1.f : 0.f, b > THR ? 1.f : 0.f);
        }
    }
}

__device__ __forceinline__ void softmax_acc(const float* __restrict__ row, int lane,
                                            float* __restrict__ accv) {
    float v[7]; float vmax = -3.0e38f;
#pragma unroll
    for (int k = 0; k < 7; k++) {
        int jj = lane + 32*k;
        v[k] = (jj < OUTN) ? row[jj] : -3.0e38f;
        vmax = fmaxf(vmax, v[k]);
    }
#pragma unroll
    for (int o = 16; o; o >>= 1) vmax = fmaxf(vmax, __shfl_xor_sync(0xffffffffu, vmax, o));
    float e[7]; float s = 0.f;
#pragma unroll
    for (int k = 0; k < 7; k++) {
        int jj = lane + 32*k;
        e[k] = (jj < OUTN) ? __expf(v[k] - vmax) : 0.f;
        s += e[k];
    }
#pragma unroll
    for (int o = 16; o; o >>= 1) s += __shfl_xor_sync(0xffffffffu, s, o);
    float inv = 1.0f / s;
#pragma unroll
    for (int k = 0; k < 7; k++) accv[k] += e[k]*inv;
}

// One independent 128-thread CTA: all 256 neurons (j0=tid, j1=tid+128),
// PT row-pairs (2*PT real batch rows starting at `start`). No dummies.
template<int PT>
__device__ __forceinline__ void run_block(
    const float* __restrict__ x,
    const float* __restrict__ b1v, const float* __restrict__ b2v,
    const float* __restrict__ b3v, const float* __restrict__ b4v,
    float* __restrict__ out, int start,
    float2* __restrict__ sb0, float2* __restrict__ sb1,
    float (* __restrict__ mo_sh)[OUTN])
{
    const int j0 = threadIdx.x;
    const int j1 = j0 + 128;
    const int wloc = j0 >> 5, lane = j0 & 31;

    float m1[4*PT], m2[4*PT], m3[4*PT], m4[4*PT], mo[4*PT];
#pragma unroll
    for (int q = 0; q < 4*PT; q++) { m1[q]=m2[q]=m3[q]=m4[q]=mo[q]=0.f; }

    const float b1a = b1v[j0], b1b = b1v[j1];
    const float b2a = b2v[j0], b2b = b2v[j1];
    const float b3a = b3v[j0], b3b = b3v[j1];
    const float b4a = b4v[j0], b4b = b4v[j1];

    // softmax rows: warp w owns row w, and row w+4 if it exists
    const int r0 = wloc;
    const int r1 = (wloc + 4 < 2*PT) ? (wloc + 4) : -1;

    float aR0[7], aR1[7];
#pragma unroll
    for (int k = 0; k < 7; k++) { aR0[k]=0.f; aR1[k]=0.f; }

    const float* W1t = g_Wt + OFF_W1;
    const float* W2t = g_Wt + OFF_W2;
    const float* W3t = g_Wt + OFF_W3;
    const float* W4t = g_Wt + OFF_W4;
    const float* WOt = g_Wt + OFF_WO;

    // x staging: thread handles up to 2 fixed (row, i) slots; pointer affine in t.
    const int elems = 2*PT*DIN;                 // 160 (PT4) or 120 (PT3)
    const int i0x = j0 % DIN,  row0 = j0 / DIN;
    const int idx1 = j0 + 128;
    const int i1x = idx1 % DIN, row1 = idx1 / DIN;
    const bool has1 = (idx1 < elems);
    const float* xp0 = x + (size_t)(start + row0)*(TSTEPS*DIN) + i0x;
    const float* xp1 = has1 ? (x + (size_t)(start + row1)*(TSTEPS*DIN) + i1x) : xp0;
    float* const sA = reinterpret_cast<float*>(sb0);
    const int off0 = ((row0 >> 1)*H + i0x)*2 + (row0 & 1);
    const int off1 = ((row1 >> 1)*H + i1x)*2 + (row1 & 1);

    float xr0 = xp0[0];
    float xr1 = xp1[0];

    u64 acc[2*PT];

    for (int t = 0; t < TSTEPS; t++) {
        // commit prefetched x_t into packed-pair layout
        sA[off0] = xr0;
        if (has1) sA[off1] = xr1;
        __syncthreads();
        // kick off x_{t+1} loads (consumed next iteration -> latency fully hidden)
        if (t + 1 < TSTEPS) {
            xr0 = xp0[(t+1)*DIN];
            xr1 = xp1[(t+1)*DIN];
        }

        gemm2<DIN,PT>(W1t, sb0, j0, acc);
        leaky2<PT>(acc, b1a, b1b, m1, sb1, j0);
        __syncthreads();
        gemm2<H,PT>(W2t, sb1, j0, acc);
        leaky2<PT>(acc, b2a, b2b, m2, sb0, j0);
        __syncthreads();
        gemm2<H,PT>(W3t, sb0, j0, acc);
        leaky2<PT>(acc, b3a, b3b, m3, sb1, j0);
        __syncthreads();
        gemm2<H,PT>(W4t, sb1, j0, acc);
        leaky2<PT>(acc, b4a, b4b, m4, sb0, j0);
        __syncthreads();
        gemm2<H,PT>(WOt, sb0, j0, acc);   // Wout cols >=200 zero-padded

        // output-layer leaky (no bias, no spike), write membranes for softmax
#pragma unroll
        for (int js = 0; js < 2; js++) {
            int j = j0 + js*128;
            if (j < OUTN) {
#pragma unroll
                for (int p = 0; p < PT; p++) {
                    float i0, i1; unpack2(acc[js*PT + p], i0, i1);
                    int mi = (js*PT + p)*2;
                    float a = mo[mi], b = mo[mi+1];
                    float ra = (a > THR) ? THR : 0.f;
                    float rb2 = (b > THR) ? THR : 0.f;
                    a = BETA*a + i0 - ra;
                    b = BETA*b + i1 - rb2;
                    mo[mi] = a; mo[mi+1] = b;
                    mo_sh[2*p  ][j] = a;
                    mo_sh[2*p+1][j] = b;
                }
            }
        }
        __syncthreads();

        if (t > 50) {
            softmax_acc(mo_sh[r0], lane, aR0);
            if (r1 >= 0) softmax_acc(mo_sh[r1], lane, aR1);
        }
        // no trailing barrier: next sb0/mo_sh writes are barrier-separated from
        // these reads (sb0 write precedes a sync; mo_sh rewrite is 6 syncs away).
    }

    // write outputs (all rows real)
    {
        size_t g = (size_t)(start + r0)*OUTN;
#pragma unroll
        for (int k = 0; k < 7; k++) {
            int jj = lane + 32*k;
            if (jj < OUTN) out[g + jj] = aR0[k];
        }
        if (r1 >= 0) {
            size_t g2 = (size_t)(start + r1)*OUTN;
#pragma unroll
            for (int k = 0; k < 7; k++) {
                int jj = lane + 32*k;
                if (jj < OUTN) out[g2 + jj] = aR1[k];
            }
        }
    }
}

__global__ void prep_weights(const float* __restrict__ W1, const float* __restrict__ W2,
                             const float* __restrict__ W3, const float* __restrict__ W4,
                             const float* __restrict__ WO) {
    int idx = blockIdx.x * blockDim.x + threadIdx.x;
    if (idx < 5120) {
        int i = idx >> 8, jj = idx & 255;
        g_Wt[OFF_W1 + idx] = W1[jj*DIN + i];
    } else if (idx < 5120 + 65536) {
        int r = idx - 5120; int i = r >> 8, jj = r & 255;
        g_Wt[OFF_W2 + r] = W2[jj*H + i];
    } else if (idx < 5120 + 2*65536) {
        int r = idx - 5120 - 65536; int i = r >> 8, jj = r & 255;
        g_Wt[OFF_W3 + r] = W3[jj*H + i];
    } else if (idx < 5120 + 3*65536) {
        int r = idx - 5120 - 2*65536; int i = r >> 8, jj = r & 255;
        g_Wt[OFF_W4 + r] = W4[jj*H + i];
    } else if (idx < WT_TOTAL) {
        int r = idx - 5120 - 3*65536; int i = r >> 8, jj = r & 255;
        g_Wt[OFF_WO + r] = (jj < OUTN) ? WO[jj*H + i] : 0.f;
    }
}

// 296 CTAs of 128 threads, 2 resident per SM (independent barrier domains).
// Blocks 0..135: PT=4 (pairs 4b..4b+3). Blocks 136..295: PT=3.
__global__ void __launch_bounds__(128, 2)
snn_main(const float* __restrict__ x,
         const float* __restrict__ b1, const float* __restrict__ b2,
         const float* __restrict__ b3, const float* __restrict__ b4,
         float* __restrict__ out) {
    __shared__ float2 sb0[4 * H];
    __shared__ float2 sb1[4 * H];
    __shared__ float  mo_sh[8][OUTN];

    const int blk = blockIdx.x;
    if (blk < 136) {
        int start = 8 * blk;                       // 4 pairs = 8 rows
        run_block<4>(x, b1, b2, b3, b4, out, start, sb0, sb1, mo_sh);
    } else {
        int start = 1088 + 6 * (blk - 136);        // 3 pairs = 6 rows
        run_block<3>(x, b1, b2, b3, b4, out, start, sb0, sb1, mo_sh);
    }
}

extern "C" void kernel_launch(void* const* d_in, const int* in_sizes, int n_in,
                              void* d_out, int out_size) {
    const float* x  = (const float*)d_in[0];
    const float* W1 = (const float*)d_in[1];
    const float* b1 = (const float*)d_in[2];
    const float* W2 = (const float*)d_in[3];
    const float* b2 = (const float*)d_in[4];
    const float* W3 = (const float*)d_in[5];
    const float* b3 = (const float*)d_in[6];
    const float* W4 = (const float*)d_in[7];
    const float* b4 = (const float*)d_in[8];
    const float* WO = (const float*)d_in[9];
    float* out = (float*)d_out;

    prep_weights<<<(WT_TOTAL + 255) / 256, 256>>>(W1, W2, W3, W4, WO);
    snn_main<<<296, 128>>>(x, b1, b2, b3, b4, out);
}

// round 8
// speedup vs baseline: 1.5249x; 1.5249x over previous
#include <cuda_runtime.h>

#define H      256
#define OUTN   200
#define DIN    20
#define TSTEPS 150
#define BETA   0.9f
#define THR    1.0f

// Transposed weights scratch: Wt[i*H + j] = W[j][i]; Wout padded to 256 cols.
// Region order gives every layer a valid overrun pad for distance-2 (8-row)
// prefetch; the tail pad covers WOt's lookahead.
#define OFF_W1 0
#define OFF_W2 5120
#define OFF_W3 (5120 + 65536)
#define OFF_W4 (5120 + 2*65536)
#define OFF_WO (5120 + 3*65536)
#define WT_TOTAL (5120 + 4*65536)
__device__ float g_Wt[WT_TOTAL + 4096];

typedef unsigned long long u64;

__device__ __forceinline__ u64 ffma2(u64 a, u64 b, u64 c) {
    u64 d;
    asm("fma.rn.f32x2 %0, %1, %2, %3;" : "=l"(d) : "l"(a), "l"(b), "l"(c));
    return d;
}
__device__ __forceinline__ u64 pack2(float w) {
    u64 d;
    asm("mov.b64 %0, {%1, %1};" : "=l"(d) : "f"(w));
    return d;
}
__device__ __forceinline__ void unpack2(u64 a, float& x, float& y) {
    asm("mov.b64 {%0, %1}, %2;" : "=f"(x), "=f"(y) : "l"(a));
}

// GEMM slice: thread computes 2 output neurons (j0, j0+128) over K inputs for
// PT packed row-pairs. JT=2 gives 2x SMEM-operand reuse. Weight prefetch uses
// a PERIOD-2 rolling buffer (cur/next, distance 8 rows) under unroll 2 so the
// rotation is fully register-renamed (zero MOVs) — R7's period-3 buffer under
// unroll 2 forced real MOV chains and regressed 50%.
// Accumulation order per (p,j) is ascending-i — bit-identical to prior rounds.
template<int K, int PT>
__device__ __forceinline__ void gemm2(const float* __restrict__ Wt,
                                      const float2* __restrict__ sb,
                                      int j0, u64* __restrict__ acc) {
#pragma unroll
    for (int q = 0; q < 2*PT; q++) acc[q] = 0ull;
    const float* __restrict__ Wa = Wt + j0;
    const float* __restrict__ Wb = Wt + j0 + 128;

    float ca[4], cb[4], na[4], nb[4];
#pragma unroll
    for (int q = 0; q < 4; q++) {
        ca[q] = Wa[q*H];       cb[q] = Wb[q*H];
        na[q] = Wa[(4+q)*H];   nb[q] = Wb[(4+q)*H];
    }
#pragma unroll 2
    for (int i = 0; i < K; i += 4) {
        float fa[4], fb[4];
#pragma unroll
        for (int q = 0; q < 4; q++) {        // prefetch group i+8 (overruns -> pad)
            fa[q] = Wa[(i+8+q)*H];
            fb[q] = Wb[(i+8+q)*H];
        }
        u64 A0 = pack2(ca[0]), A1 = pack2(ca[1]), A2 = pack2(ca[2]), A3 = pack2(ca[3]);
        u64 B0 = pack2(cb[0]), B1 = pack2(cb[1]), B2 = pack2(cb[2]), B3 = pack2(cb[3]);
#pragma unroll
        for (int p = 0; p < PT; p++) {
            const ulonglong2* s = reinterpret_cast<const ulonglong2*>(sb + p*H + i);
            ulonglong2 ab = s[0];   // pairs (i),(i+1) — already f32x2-packed
            ulonglong2 cd = s[1];   // pairs (i+2),(i+3)
            acc[p]    = ffma2(A0, ab.x, acc[p]);
            acc[p]    = ffma2(A1, ab.y, acc[p]);
            acc[p]    = ffma2(A2, cd.x, acc[p]);
            acc[p]    = ffma2(A3, cd.y, acc[p]);
            acc[PT+p] = ffma2(B0, ab.x, acc[PT+p]);
            acc[PT+p] = ffma2(B1, ab.y, acc[PT+p]);
            acc[PT+p] = ffma2(B2, cd.x, acc[PT+p]);
            acc[PT+p] = ffma2(B3, cd.y, acc[PT+p]);
        }
#pragma unroll
        for (int q = 0; q < 4; q++) { ca[q]=na[q]; cb[q]=nb[q]; na[q]=fa[q]; nb[q]=fb[q]; }
    }
}

// Leaky update (reset from PREVIOUS membrane, subtract) + spike write, 2 j's.
template<int PT>
__device__ __forceinline__ void leaky2(const u64* __restrict__ acc, float c0, float c1,
                                       float* __restrict__ m, float2* __restrict__ dst,
                                       int j0) {
#pragma unroll
    for (int js = 0; js < 2; js++) {
        float bs = js ? c1 : c0;
        int j = j0 + js*128;
#pragma unroll
        for (int p = 0; p < PT; p++) {
            float i0, i1; unpack2(acc[js*PT + p], i0, i1);
            int mi = (js*PT + p)*2;
            float a = m[mi], b = m[mi+1];
            float ra = (a > THR) ? THR : 0.f;
            float rb = (b > THR) ? THR : 0.f;
            a = BETA*a + (i0 + bs) - ra;
            b = BETA*b + (i1 + bs) - rb;
            m[mi] = a; m[mi+1] = b;
            dst[p*H + j] = make_float2(a > THR ? 1.f : 0.f, b > THR ? 1.f : 0.f);
        }
    }
}

__device__ __forceinline__ void softmax_acc(const float* __restrict__ row, int lane,
                                            float* __restrict__ accv) {
    float v[7]; float vmax = -3.0e38f;
#pragma unroll
    for (int k = 0; k < 7; k++) {
        int jj = lane + 32*k;
        v[k] = (jj < OUTN) ? row[jj] : -3.0e38f;
        vmax = fmaxf(vmax, v[k]);
    }
#pragma unroll
    for (int o = 16; o; o >>= 1) vmax = fmaxf(vmax, __shfl_xor_sync(0xffffffffu, vmax, o));
    float e[7]; float s = 0.f;
#pragma unroll
    for (int k = 0; k < 7; k++) {
        int jj = lane + 32*k;
        e[k] = (jj < OUTN) ? __expf(v[k] - vmax) : 0.f;
        s += e[k];
    }
#pragma unroll
    for (int o = 16; o; o >>= 1) s += __shfl_xor_sync(0xffffffffu, s, o);
    float inv = 1.0f / s;
#pragma unroll
    for (int k = 0; k < 7; k++) accv[k] += e[k]*inv;
}

// One independent 128-thread CTA: all 256 neurons (j0=tid, j1=tid+128),
// PT row-pairs (2*PT real batch rows starting at `start`). No dummies.
template<int PT>
__device__ __forceinline__ void run_block(
    const float* __restrict__ x,
    const float* __restrict__ b1v, const float* __restrict__ b2v,
    const float* __restrict__ b3v, const float* __restrict__ b4v,
    float* __restrict__ out, int start,
    float2* __restrict__ sb0, float2* __restrict__ sb1,
    float (* __restrict__ mo_sh)[OUTN])
{
    const int j0 = threadIdx.x;
    const int j1 = j0 + 128;
    const int wloc = j0 >> 5, lane = j0 & 31;

    float m1[4*PT], m2[4*PT], m3[4*PT], m4[4*PT], mo[4*PT];
#pragma unroll
    for (int q = 0; q < 4*PT; q++) { m1[q]=m2[q]=m3[q]=m4[q]=mo[q]=0.f; }

    const float b1a = b1v[j0], b1b = b1v[j1];
    const float b2a = b2v[j0], b2b = b2v[j1];
    const float b3a = b3v[j0], b3b = b3v[j1];
    const float b4a = b4v[j0], b4b = b4v[j1];

    // softmax rows: warp w owns row w, and row w+4 if it exists
    const int r0 = wloc;
    const int r1 = (wloc + 4 < 2*PT) ? (wloc + 4) : -1;

    float aR0[7], aR1[7];
#pragma unroll
    for (int k = 0; k < 7; k++) { aR0[k]=0.f; aR1[k]=0.f; }

    const float* W1t = g_Wt + OFF_W1;
    const float* W2t = g_Wt + OFF_W2;
    const float* W3t = g_Wt + OFF_W3;
    const float* W4t = g_Wt + OFF_W4;
    const float* WOt = g_Wt + OFF_WO;

    // x staging: thread handles up to 2 fixed (row, i) slots; pointer affine in t.
    const int elems = 2*PT*DIN;                 // 160 (PT4) or 120 (PT3)
    const int i0x = j0 % DIN,  row0 = j0 / DIN;
    const int idx1 = j0 + 128;
    const int i1x = idx1 % DIN, row1 = idx1 / DIN;
    const bool has1 = (idx1 < elems);
    const float* xp0 = x + (size_t)(start + row0)*(TSTEPS*DIN) + i0x;
    const float* xp1 = has1 ? (x + (size_t)(start + row1)*(TSTEPS*DIN) + i1x) : xp0;
    float* const sA = reinterpret_cast<float*>(sb0);
    const int off0 = ((row0 >> 1)*H + i0x)*2 + (row0 & 1);
    const int off1 = ((row1 >> 1)*H + i1x)*2 + (row1 & 1);

    float xr0 = xp0[0];
    float xr1 = xp1[0];

    u64 acc[2*PT];

    for (int t = 0; t < TSTEPS; t++) {
        // commit prefetched x_t into packed-pair layout
        sA[off0] = xr0;
        if (has1) sA[off1] = xr1;
        __syncthreads();
        // kick off x_{t+1} loads (consumed next iteration -> latency fully hidden)
        if (t + 1 < TSTEPS) {
            xr0 = xp0[(t+1)*DIN];
            xr1 = xp1[(t+1)*DIN];
        }

        gemm2<DIN,PT>(W1t, sb0, j0, acc);
        leaky2<PT>(acc, b1a, b1b, m1, sb1, j0);
        __syncthreads();
        gemm2<H,PT>(W2t, sb1, j0, acc);
        leaky2<PT>(acc, b2a, b2b, m2, sb0, j0);
        __syncthreads();
        gemm2<H,PT>(W3t, sb0, j0, acc);
        leaky2<PT>(acc, b3a, b3b, m3, sb1, j0);
        __syncthreads();
        gemm2<H,PT>(W4t, sb1, j0, acc);
        leaky2<PT>(acc, b4a, b4b, m4, sb0, j0);
        __syncthreads();
        gemm2<H,PT>(WOt, sb0, j0, acc);   // Wout cols >=200 zero-padded

        // output-layer leaky (no bias, no spike), write membranes for softmax
#pragma unroll
        for (int js = 0; js < 2; js++) {
            int j = j0 + js*128;
            if (j < OUTN) {
#pragma unroll
                for (int p = 0; p < PT; p++) {
                    float i0, i1; unpack2(acc[js*PT + p], i0, i1);
                    int mi = (js*PT + p)*2;
                    float a = mo[mi], b = mo[mi+1];
                    float ra = (a > THR) ? THR : 0.f;
                    float rb2 = (b > THR) ? THR : 0.f;
                    a = BETA*a + i0 - ra;
                    b = BETA*b + i1 - rb2;
                    mo[mi] = a; mo[mi+1] = b;
                    mo_sh[2*p  ][j] = a;
                    mo_sh[2*p+1][j] = b;
                }
            }
        }
        __syncthreads();

        if (t > 50) {
            softmax_acc(mo_sh[r0], lane, aR0);
            if (r1 >= 0) softmax_acc(mo_sh[r1], lane, aR1);
        }
        // no trailing barrier: next sb0/mo_sh writes are barrier-separated from
        // these reads (sb0 write precedes a sync; mo_sh rewrite is 6 syncs away).
    }

    // write outputs (all rows real)
    {
        size_t g = (size_t)(start + r0)*OUTN;
#pragma unroll
        for (int k = 0; k < 7; k++) {
            int jj = lane + 32*k;
            if (jj < OUTN) out[g + jj] = aR0[k];
        }
        if (r1 >= 0) {
            size_t g2 = (size_t)(start + r1)*OUTN;
#pragma unroll
            for (int k = 0; k < 7; k++) {
                int jj = lane + 32*k;
                if (jj < OUTN) out[g2 + jj] = aR1[k];
            }
        }
    }
}

__global__ void prep_weights(const float* __restrict__ W1, const float* __restrict__ W2,
                             const float* __restrict__ W3, const float* __restrict__ W4,
                             const float* __restrict__ WO) {
    int idx = blockIdx.x * blockDim.x + threadIdx.x;
    if (idx < 5120) {
        int i = idx >> 8, jj = idx & 255;
        g_Wt[OFF_W1 + idx] = W1[jj*DIN + i];
    } else if (idx < 5120 + 65536) {
        int r = idx - 5120; int i = r >> 8, jj = r & 255;
        g_Wt[OFF_W2 + r] = W2[jj*H + i];
    } else if (idx < 5120 + 2*65536) {
        int r = idx - 5120 - 65536; int i = r >> 8, jj = r & 255;
        g_Wt[OFF_W3 + r] = W3[jj*H + i];
    } else if (idx < 5120 + 3*65536) {
        int r = idx - 5120 - 2*65536; int i = r >> 8, jj = r & 255;
        g_Wt[OFF_W4 + r] = W4[jj*H + i];
    } else if (idx < WT_TOTAL) {
        int r = idx - 5120 - 3*65536; int i = r >> 8, jj = r & 255;
        g_Wt[OFF_WO + r] = (jj < OUTN) ? WO[jj*H + i] : 0.f;
    }
}

// 296 CTAs of 128 threads, 2 resident per SM (independent barrier domains).
// Blocks 0..135: PT=4 (8 rows each). Blocks 136..295: PT=3 (6 rows each).
__global__ void __launch_bounds__(128, 2)
snn_main(const float* __restrict__ x,
         const float* __restrict__ b1, const float* __restrict__ b2,
         const float* __restrict__ b3, const float* __restrict__ b4,
         float* __restrict__ out) {
    __shared__ float2 sb0[4 * H];
    __shared__ float2 sb1[4 * H];
    __shared__ float  mo_sh[8][OUTN];

    const int blk = blockIdx.x;
    if (blk < 136) {
        int start = 8 * blk;                       // 4 pairs = 8 rows
        run_block<4>(x, b1, b2, b3, b4, out, start, sb0, sb1, mo_sh);
    } else {
        int start = 1088 + 6 * (blk - 136);        // 3 pairs = 6 rows
        run_block<3>(x, b1, b2, b3, b4, out, start, sb0, sb1, mo_sh);
    }
}

extern "C" void kernel_launch(void* const* d_in, const int* in_sizes, int n_in,
                              void* d_out, int out_size) {
    const float* x  = (const float*)d_in[0];
    const float* W1 = (const float*)d_in[1];
    const float* b1 = (const float*)d_in[2];
    const float* W2 = (const float*)d_in[3];
    const float* b2 = (const float*)d_in[4];
    const float* W3 = (const float*)d_in[5];
    const float* b3 = (const float*)d_in[6];
    const float* W4 = (const float*)d_in[7];
    const float* b4 = (const float*)d_in[8];
    const float* WO = (const float*)d_in[9];
    float* out = (float*)d_out;

    prep_weights<<<(WT_TOTAL + 255) / 256, 256>>>(W1, W2, W3, W4, WO);
    snn_main<<<296, 128>>>(x, b1, b2, b3, b4, out);
}